// round 7
// baseline (speedup 1.0000x reference)
#include <cuda_runtime.h>
#include <cuda_fp16.h>
#include <cstdint>

#define B_SZ   4096
#define D_SZ   512
#define MARGIN 0.5f
#define EPSV   1e-6f
#define BIGV   1e9f

#define NSPLIT (B_SZ / 128)                  // 32 tile rows/cols
#define NTILES (NSPLIT * (NSPLIT + 1) / 2)   // 528 upper-triangle tiles
#define STG    32768                         // bytes per stage (A 16K + B 16K)
#define DYN_SMEM (3 * STG)
#define NCTA   296                           // 2 per SM x 148 SMs, all resident
#define CBLKS  16

// ---------------- device scratch (no cudaMalloc allowed) ----------------
__device__ __half Ehalf[B_SZ * D_SZ];
__device__ float  g_q[B_SZ];
__device__ float  g_p[B_SZ];
__device__ float  g_hp[NSPLIT][B_SZ];
__device__ float  g_hn[NSPLIT][B_SZ];
__device__ float  g_psum[CBLKS];
__device__ float  g_pcnt[CBLKS];
__device__ unsigned bar_cnt[3];
__device__ unsigned bar_gen[3];

// ---------------- helpers ----------------
__device__ __forceinline__ uint32_t smem_u32(const void* p) {
    uint32_t a;
    asm("{ .reg .u64 t; cvta.to.shared.u64 t, %1; cvt.u32.u64 %0, t; }" : "=r"(a) : "l"(p));
    return a;
}

#define LDMATRIX_X4(r, addr)                                                      \
    asm volatile("ldmatrix.sync.aligned.m8n8.x4.shared.b16 {%0,%1,%2,%3}, [%4];"  \
        : "=r"((r)[0]), "=r"((r)[1]), "=r"((r)[2]), "=r"((r)[3]) : "r"(addr))

#define MMA16816(D, A, b0, b1)                                                    \
    asm volatile("mma.sync.aligned.m16n8k16.row.col.f32.f16.f16.f32 "             \
        "{%0,%1,%2,%3}, {%4,%5,%6,%7}, {%8,%9}, {%0,%1,%2,%3};"                   \
        : "+f"((D)[0]), "+f"((D)[1]), "+f"((D)[2]), "+f"((D)[3])                  \
        : "r"((A)[0]), "r"((A)[1]), "r"((A)[2]), "r"((A)[3]), "r"(b0), "r"(b1))

#define CP_ASYNC16(dst, src)                                                      \
    asm volatile("cp.async.cg.shared.global [%0], [%1], 16;"                      \
        :: "r"(dst), "l"(src) : "memory")
#define CP_COMMIT() asm volatile("cp.async.commit_group;" ::: "memory")

// sense-reversing global barrier (self-resetting across graph replays)
__device__ __forceinline__ void grid_barrier(int i) {
    __syncthreads();
    if (threadIdx.x == 0) {
        __threadfence();
        unsigned g = atomicAdd(&bar_gen[i], 0u);
        unsigned old = atomicAdd(&bar_cnt[i], 1u);
        if (old == NCTA - 1) {
            bar_cnt[i] = 0;
            __threadfence();
            atomicAdd(&bar_gen[i], 1u);
        } else {
            while (atomicAdd(&bar_gen[i], 0u) == g) { __nanosleep(32); }
        }
        __threadfence();
    }
    __syncthreads();
}

__device__ __forceinline__ void grid_arrive(int i) {
    __syncthreads();
    if (threadIdx.x == 0) {
        __threadfence();
        unsigned old = atomicAdd(&bar_cnt[i], 1u);
        if (old == NCTA - 1) {
            bar_cnt[i] = 0;
            __threadfence();
            atomicAdd(&bar_gen[i], 1u);
        }
    }
}

// load one 128x64-fp16 A tile (+ B tile unless diag) into a stage (xor swizzle)
__device__ __forceinline__ void load_stage(uint32_t base, int i0, int j0,
                                           int kc, int tid, bool diag) {
    uint32_t As = base, Bs = base + 16384;
#pragma unroll
    for (int it = 0; it < 4; it++) {
        int idx = tid + it * 256;
        int r = idx >> 3, ch = idx & 7;
        uint32_t dst = As + r * 128 + ((ch ^ (r & 7)) << 4);
        const void* src = &Ehalf[(size_t)(i0 + r) * D_SZ + kc + ch * 8];
        CP_ASYNC16(dst, src);
    }
    if (!diag) {
#pragma unroll
        for (int it = 0; it < 4; it++) {
            int idx = tid + it * 256;
            int r = idx >> 3, ch = idx & 7;
            uint32_t dst = Bs + r * 128 + ((ch ^ (r & 7)) << 4);
            const void* src = &Ehalf[(size_t)(j0 + r) * D_SZ + kc + ch * 8];
            CP_ASYNC16(dst, src);
        }
    }
}

// ---------------------------------------------------------------------------
// Single fused persistent kernel.
// ---------------------------------------------------------------------------
__global__ void __launch_bounds__(256, 2)
fused_triplet_kernel(const float* __restrict__ E,
                     const int* __restrict__ lab,
                     float* __restrict__ out) {
    extern __shared__ __align__(1024) char dsm[];
    __shared__ int   s_labi[128];
    __shared__ int   s_labj[128];
    __shared__ float s_qi[128];
    __shared__ float s_qj[128];
    __shared__ float hp_s[128][4];
    __shared__ float hn_s[128][4];
    __shared__ float hp_cs[128][2];
    __shared__ float hn_cs[128][2];
    __shared__ int   c_cnt[512];
    __shared__ float c_sum[256], c_cn[256];

    const int tid  = threadIdx.x;
    const int bid  = blockIdx.x;
    const int wid  = tid >> 5, lane = tid & 31;
    const uint32_t smem = smem_u32(dsm);

    // ===== Phase A: fp32->fp16 convert + per-row stats =====
    for (int row = bid * 8 + wid; row < B_SZ; row += NCTA * 8) {
        const float4* rp = reinterpret_cast<const float4*>(E + (size_t)row * D_SZ);
        uint2* hout = reinterpret_cast<uint2*>(Ehalf + (size_t)row * D_SZ);
        float s = 0.f, sq = 0.f;
#pragma unroll
        for (int q = 0; q < 4; q++) {
            float4 v = rp[lane + 32 * q];
            s  += v.x + v.y + v.z + v.w;
            sq += v.x * v.x + v.y * v.y + v.z * v.z + v.w * v.w;
            __half2 h0 = __floats2half2_rn(v.x, v.y);
            __half2 h1 = __floats2half2_rn(v.z, v.w);
            uint2 packed;
            packed.x = *reinterpret_cast<uint32_t*>(&h0);
            packed.y = *reinterpret_cast<uint32_t*>(&h1);
            hout[lane + 32 * q] = packed;
        }
#pragma unroll
        for (int off = 16; off > 0; off >>= 1) {
            s  += __shfl_xor_sync(0xffffffffu, s,  off);
            sq += __shfl_xor_sync(0xffffffffu, sq, off);
        }
        if (lane == 0) {
            g_q[row] = sq - 2.f * EPSV * s;
            g_p[row] = sq + 2.f * EPSV * s + (float)D_SZ * EPSV * EPSV;
        }
    }
    grid_barrier(0);

    // ===== Phase B: persistent upper-triangle gram tiles =====
    const int wr = wid >> 2, wc = wid & 3;          // 2 x 4 warp grid
    for (int t = bid; t < NTILES; t += NCTA) {
        int ti = 0, rem = t;
        while (rem >= NSPLIT - ti) { rem -= NSPLIT - ti; ti++; }
        const int tj = ti + rem;
        const bool diag = (ti == tj);
        const int i0 = ti * 128, j0 = tj * 128;

        __syncthreads();            // protect smem metadata reuse across tiles
        if (tid < 128) {
            s_labi[tid] = lab[i0 + tid];
            s_labj[tid] = lab[j0 + tid];
            s_qi[tid]   = g_q[i0 + tid];
            s_qj[tid]   = g_q[j0 + tid];
        }

        float d[4][4][4];
#pragma unroll
        for (int a = 0; a < 4; a++)
#pragma unroll
            for (int b = 0; b < 4; b++)
#pragma unroll
                for (int e = 0; e < 4; e++) d[a][b][e] = 0.f;

        load_stage(smem + 0 * STG, i0, j0, 0,  tid, diag); CP_COMMIT();
        load_stage(smem + 1 * STG, i0, j0, 64, tid, diag); CP_COMMIT();

#pragma unroll 1
        for (int c = 0; c < 8; c++) {
            if (c == 7) asm volatile("cp.async.wait_group 0;" ::: "memory");
            else        asm volatile("cp.async.wait_group 1;" ::: "memory");
            __syncthreads();
            if (c + 2 < 8) {
                load_stage(smem + ((c + 2) % 3) * STG, i0, j0, (c + 2) * 64, tid, diag);
                CP_COMMIT();
            }
            const uint32_t As = smem + (c % 3) * STG;
            const uint32_t Bs = diag ? As : (As + 16384);
#pragma unroll
            for (int ks = 0; ks < 4; ks++) {
                uint32_t a[4][4];
#pragma unroll
                for (int mt = 0; mt < 4; mt++) {
                    int arow = wr * 64 + mt * 16 + (lane & 15);
                    uint32_t ad = As + arow * 128 +
                                  ((((ks << 1) | (lane >> 4)) ^ (arow & 7)) << 4);
                    LDMATRIX_X4(a[mt], ad);
                }
#pragma unroll
                for (int np = 0; np < 2; np++) {
                    int brow = wc * 32 + np * 16 + (lane & 15);
                    uint32_t bd = Bs + brow * 128 +
                                  ((((ks << 1) | (lane >> 4)) ^ (brow & 7)) << 4);
                    uint32_t b[4];
                    LDMATRIX_X4(b, bd);
#pragma unroll
                    for (int mt = 0; mt < 4; mt++) {
                        MMA16816(d[mt][2 * np],     a[mt], b[0], b[2]);
                        MMA16816(d[mt][2 * np + 1], a[mt], b[1], b[3]);
                    }
                }
            }
        }

        // dual-sided epilogue
        float hpc[8], hnc[8];
#pragma unroll
        for (int k = 0; k < 8; k++) { hpc[k] = -BIGV; hnc[k] = BIGV; }

#pragma unroll
        for (int mt = 0; mt < 4; mt++) {
            int r0 = wr * 64 + mt * 16 + (lane >> 2);
            int li0 = s_labi[r0], li1 = s_labi[r0 + 8];
            float qi0 = s_qi[r0], qi1 = s_qi[r0 + 8];
            float hp0 = -BIGV, hp1 = -BIGV, hn0 = BIGV, hn1 = BIGV;
#pragma unroll
            for (int nt = 0; nt < 4; nt++) {
                int c0 = wc * 32 + nt * 8 + ((lane & 3) << 1);
                float q0 = s_qj[c0], q1 = s_qj[c0 + 1];
                int lj0 = s_labj[c0], lj1 = s_labj[c0 + 1];
                float g00 = d[mt][nt][0], g01 = d[mt][nt][1];
                float g10 = d[mt][nt][2], g11 = d[mt][nt][3];
                bool e00 = (li0 == lj0), e01 = (li0 == lj1);
                bool e10 = (li1 == lj0), e11 = (li1 == lj1);
                float m00 = fmaf(g00, -2.f, q0);
                float m01 = fmaf(g01, -2.f, q1);
                float m10 = fmaf(g10, -2.f, q0);
                float m11 = fmaf(g11, -2.f, q1);
                if (e00) hp0 = fmaxf(hp0, m00); else hn0 = fminf(hn0, m00);
                if (e01) hp0 = fmaxf(hp0, m01); else hn0 = fminf(hn0, m01);
                if (e10) hp1 = fmaxf(hp1, m10); else hn1 = fminf(hn1, m10);
                if (e11) hp1 = fmaxf(hp1, m11); else hn1 = fminf(hn1, m11);
                if (!diag) {
                    float n00 = fmaf(g00, -2.f, qi0);
                    float n01 = fmaf(g01, -2.f, qi0);
                    float n10 = fmaf(g10, -2.f, qi1);
                    float n11 = fmaf(g11, -2.f, qi1);
                    int k0 = nt * 2, k1 = nt * 2 + 1;
                    if (e00) hpc[k0] = fmaxf(hpc[k0], n00); else hnc[k0] = fminf(hnc[k0], n00);
                    if (e10) hpc[k0] = fmaxf(hpc[k0], n10); else hnc[k0] = fminf(hnc[k0], n10);
                    if (e01) hpc[k1] = fmaxf(hpc[k1], n01); else hnc[k1] = fminf(hnc[k1], n01);
                    if (e11) hpc[k1] = fmaxf(hpc[k1], n11); else hnc[k1] = fminf(hnc[k1], n11);
                }
            }
#pragma unroll
            for (int off = 1; off < 4; off <<= 1) {
                hp0 = fmaxf(hp0, __shfl_xor_sync(0xffffffffu, hp0, off));
                hp1 = fmaxf(hp1, __shfl_xor_sync(0xffffffffu, hp1, off));
                hn0 = fminf(hn0, __shfl_xor_sync(0xffffffffu, hn0, off));
                hn1 = fminf(hn1, __shfl_xor_sync(0xffffffffu, hn1, off));
            }
            if ((lane & 3) == 0) {
                hp_s[r0][wc] = hp0; hp_s[r0 + 8][wc] = hp1;
                hn_s[r0][wc] = hn0; hn_s[r0 + 8][wc] = hn1;
            }
        }

        if (!diag) {
#pragma unroll
            for (int off = 4; off <= 16; off <<= 1) {
#pragma unroll
                for (int k = 0; k < 8; k++) {
                    hpc[k] = fmaxf(hpc[k], __shfl_xor_sync(0xffffffffu, hpc[k], off));
                    hnc[k] = fminf(hnc[k], __shfl_xor_sync(0xffffffffu, hnc[k], off));
                }
            }
            if ((lane >> 2) == 0) {
#pragma unroll
                for (int k = 0; k < 8; k++) {
                    int col = wc * 32 + (k >> 1) * 8 + ((lane & 3) << 1) + (k & 1);
                    hp_cs[col][wr] = hpc[k];
                    hn_cs[col][wr] = hnc[k];
                }
            }
        }
        __syncthreads();
        if (tid < 128) {
            float hp = fmaxf(fmaxf(hp_s[tid][0], hp_s[tid][1]),
                             fmaxf(hp_s[tid][2], hp_s[tid][3]));
            float hn = fminf(fminf(hn_s[tid][0], hn_s[tid][1]),
                             fminf(hn_s[tid][2], hn_s[tid][3]));
            g_hp[tj][i0 + tid] = hp;
            g_hn[tj][i0 + tid] = hn;
            if (!diag) {
                float hpc2 = fmaxf(hp_cs[tid][0], hp_cs[tid][1]);
                float hnc2 = fminf(hn_cs[tid][0], hn_cs[tid][1]);
                g_hp[ti][j0 + tid] = hpc2;
                g_hn[ti][j0 + tid] = hnc2;
            }
        }
    }

    // ===== Phase C: combine (16 CTAs) + final reduce (CTA 0) =====
    if (bid < CBLKS) {
        grid_barrier(1);

        for (int i = tid; i < 512; i += 256) c_cnt[i] = 0;
        __syncthreads();
        for (int i = tid; i < B_SZ; i += 256) atomicAdd(&c_cnt[lab[i]], 1);
        __syncthreads();

        const int row = bid * 256 + tid;
        float hp = -BIGV, hn = BIGV;
#pragma unroll
        for (int s = 0; s < NSPLIT; s++) {
            hp = fmaxf(hp, g_hp[s][row]);
            hn = fminf(hn, g_hn[s][row]);
        }
        int k = c_cnt[lab[row]];
        bool valid = (k >= 2) && (k < B_SZ);
        float p = g_p[row];
        float dp = sqrtf(fmaxf(p + hp, 0.f));
        float dn = sqrtf(fmaxf(p + hn, 0.f));
        float v = dp - dn + MARGIN;
        c_sum[tid] = valid ? ((v > 0.f) ? v : 0.f) : 0.f;
        c_cn[tid]  = valid ? 1.f : 0.f;
        __syncthreads();
        for (int off = 128; off > 0; off >>= 1) {
            if (tid < off) { c_sum[tid] += c_sum[tid + off]; c_cn[tid] += c_cn[tid + off]; }
            __syncthreads();
        }
        if (tid == 0) { g_psum[bid] = c_sum[0]; g_pcnt[bid] = c_cn[0]; }

        if (bid == 0) {
            grid_barrier(2);
            if (wid == 0) {
                float s = (lane < CBLKS) ? g_psum[lane] : 0.f;
                float c = (lane < CBLKS) ? g_pcnt[lane] : 0.f;
#pragma unroll
                for (int off = 16; off > 0; off >>= 1) {
                    s += __shfl_xor_sync(0xffffffffu, s, off);
                    c += __shfl_xor_sync(0xffffffffu, c, off);
                }
                if (lane == 0) out[0] = (c > 0.f) ? (s / c) : 0.f;
            }
        } else {
            grid_arrive(2);
        }
    } else {
        grid_arrive(1);
        grid_arrive(2);
    }
}

// ---------------------------------------------------------------------------
extern "C" void kernel_launch(void* const* d_in, const int* in_sizes, int n_in,
                              void* d_out, int out_size) {
    const float* E   = (const float*)d_in[0];
    const int*   lab = (const int*)d_in[1];
    float*       out = (float*)d_out;
    (void)in_sizes; (void)n_in; (void)out_size;

    cudaFuncSetAttribute(fused_triplet_kernel,
                         cudaFuncAttributeMaxDynamicSharedMemorySize, DYN_SMEM);
    fused_triplet_kernel<<<NCTA, 256, DYN_SMEM>>>(E, lab, out);
}

// round 8
// speedup vs baseline: 1.1185x; 1.1185x over previous
#include <cuda_runtime.h>
#include <cuda_fp16.h>
#include <cstdint>

#define B_SZ   4096
#define D_SZ   512
#define MARGIN 0.5f
#define EPSV   1e-6f
#define BIGV   1e9f

#define NSPLIT (B_SZ / 128)                  // 32 tile rows/cols
#define NTILES (NSPLIT * (NSPLIT + 1) / 2)   // 528 upper-triangle tiles
#define STG    32768                         // bytes per stage (A 16K + B 16K)
#define DYN_SMEM (3 * STG)
#define CBLKS  16

// ---------------- device scratch (no cudaMalloc allowed) ----------------
__device__ __half Ehalf[B_SZ * D_SZ];
__device__ float  g_q[B_SZ];
__device__ float  g_p[B_SZ];
__device__ float  g_hp[NSPLIT][B_SZ];
__device__ float  g_hn[NSPLIT][B_SZ];
__device__ float  g_psum[CBLKS];
__device__ float  g_pcnt[CBLKS];
__device__ unsigned g_done;

// ---------------- helpers ----------------
__device__ __forceinline__ uint32_t smem_u32(const void* p) {
    uint32_t a;
    asm("{ .reg .u64 t; cvta.to.shared.u64 t, %1; cvt.u32.u64 %0, t; }" : "=r"(a) : "l"(p));
    return a;
}

#define LDMATRIX_X4(r, addr)                                                      \
    asm volatile("ldmatrix.sync.aligned.m8n8.x4.shared.b16 {%0,%1,%2,%3}, [%4];"  \
        : "=r"((r)[0]), "=r"((r)[1]), "=r"((r)[2]), "=r"((r)[3]) : "r"(addr))

#define MMA16816(D, A, b0, b1)                                                    \
    asm volatile("mma.sync.aligned.m16n8k16.row.col.f32.f16.f16.f32 "             \
        "{%0,%1,%2,%3}, {%4,%5,%6,%7}, {%8,%9}, {%0,%1,%2,%3};"                   \
        : "+f"((D)[0]), "+f"((D)[1]), "+f"((D)[2]), "+f"((D)[3])                  \
        : "r"((A)[0]), "r"((A)[1]), "r"((A)[2]), "r"((A)[3]), "r"(b0), "r"(b1))

#define CP_ASYNC16(dst, src)                                                      \
    asm volatile("cp.async.cg.shared.global [%0], [%1], 16;"                      \
        :: "r"(dst), "l"(src) : "memory")
#define CP_COMMIT() asm volatile("cp.async.commit_group;" ::: "memory")

// load one 128x64-fp16 A tile (+ B tile unless diag) into a stage (xor swizzle)
// 128 threads: 8 chunks of 16B each per tile side.
__device__ __forceinline__ void load_stage(uint32_t base, int i0, int j0,
                                           int kc, int tid, bool diag) {
    uint32_t As = base, Bs = base + 16384;
#pragma unroll
    for (int it = 0; it < 8; it++) {
        int idx = tid + it * 128;
        int r = idx >> 3, ch = idx & 7;
        uint32_t dst = As + r * 128 + ((ch ^ (r & 7)) << 4);
        const void* src = &Ehalf[(size_t)(i0 + r) * D_SZ + kc + ch * 8];
        CP_ASYNC16(dst, src);
    }
    if (!diag) {
#pragma unroll
        for (int it = 0; it < 8; it++) {
            int idx = tid + it * 128;
            int r = idx >> 3, ch = idx & 7;
            uint32_t dst = Bs + r * 128 + ((ch ^ (r & 7)) << 4);
            const void* src = &Ehalf[(size_t)(j0 + r) * D_SZ + kc + ch * 8];
            CP_ASYNC16(dst, src);
        }
    }
}

// ---------------------------------------------------------------------------
// Kernel 1: fused fp32->fp16 convert + per-row stats. One warp per row.
// ---------------------------------------------------------------------------
__global__ void prep_stats_kernel(const float* __restrict__ E) {
    int warp = (blockIdx.x * blockDim.x + threadIdx.x) >> 5;
    int lane = threadIdx.x & 31;
    const float4* row = reinterpret_cast<const float4*>(E + (size_t)warp * D_SZ);
    uint2* hout = reinterpret_cast<uint2*>(Ehalf + (size_t)warp * D_SZ);
    float s = 0.f, sq = 0.f;
#pragma unroll
    for (int q = 0; q < 4; q++) {
        float4 v = row[lane + 32 * q];
        s  += v.x + v.y + v.z + v.w;
        sq += v.x * v.x + v.y * v.y + v.z * v.z + v.w * v.w;
        __half2 h0 = __floats2half2_rn(v.x, v.y);
        __half2 h1 = __floats2half2_rn(v.z, v.w);
        uint2 packed;
        packed.x = *reinterpret_cast<uint32_t*>(&h0);
        packed.y = *reinterpret_cast<uint32_t*>(&h1);
        hout[lane + 32 * q] = packed;
    }
#pragma unroll
    for (int off = 16; off > 0; off >>= 1) {
        s  += __shfl_xor_sync(0xffffffffu, s,  off);
        sq += __shfl_xor_sync(0xffffffffu, sq, off);
    }
    if (lane == 0) {
        g_q[warp] = sq - 2.f * EPSV * s;
        g_p[warp] = sq + 2.f * EPSV * s + (float)D_SZ * EPSV * EPSV;
    }
}

// ---------------------------------------------------------------------------
// Kernel 2: upper-triangle 128x128x512 gram tile, 4 warps, 64x64 warp tile,
// double-buffered fragments, dual-sided epilogue.
// ---------------------------------------------------------------------------
__global__ void __launch_bounds__(128, 2)
gemm_triplet_kernel(const int* __restrict__ lab) {
    extern __shared__ __align__(1024) char dsm[];
    __shared__ int   s_labi[128];
    __shared__ int   s_labj[128];
    __shared__ float s_qi[128];
    __shared__ float s_qj[128];
    __shared__ float hp_s[128][2];
    __shared__ float hn_s[128][2];
    __shared__ float hp_cs[128][2];
    __shared__ float hn_cs[128][2];

    // map linear block id -> upper-triangle (ti, tj), ti <= tj
    int bid = blockIdx.x;
    int ti = 0, rem = bid;
    while (rem >= NSPLIT - ti) { rem -= NSPLIT - ti; ti++; }
    const int tj = ti + rem;
    const bool diag = (ti == tj);

    const int tid  = threadIdx.x;
    const int wid  = tid >> 5, lane = tid & 31;
    const int wr   = wid >> 1, wc = wid & 1;        // 2 x 2 warp grid
    const int hl   = lane >> 4;
    const int l15  = lane & 15;
    const int i0   = ti * 128;
    const int j0   = tj * 128;
    const uint32_t smem = smem_u32(dsm);

    s_labi[tid] = lab[i0 + tid];
    s_labj[tid] = lab[j0 + tid];
    s_qi[tid]   = g_q[i0 + tid];
    s_qj[tid]   = g_q[j0 + tid];

    float d[4][8][4];
#pragma unroll
    for (int a = 0; a < 4; a++)
#pragma unroll
        for (int b = 0; b < 8; b++)
#pragma unroll
            for (int e = 0; e < 4; e++) d[a][b][e] = 0.f;

    load_stage(smem + 0 * STG, i0, j0, 0,  tid, diag); CP_COMMIT();
    load_stage(smem + 1 * STG, i0, j0, 64, tid, diag); CP_COMMIT();

#define LOAD_FRAGS(abuf, bbuf, ksv) do {                                          \
    _Pragma("unroll")                                                             \
    for (int mt = 0; mt < 4; mt++) {                                              \
        int arow = wr * 64 + mt * 16 + l15;                                       \
        uint32_t ad = As + arow * 128 +                                           \
                      (((((ksv) << 1) | hl) ^ (arow & 7)) << 4);                  \
        LDMATRIX_X4((abuf)[mt], ad);                                              \
    }                                                                             \
    _Pragma("unroll")                                                             \
    for (int np = 0; np < 4; np++) {                                              \
        int brow = wc * 64 + np * 16 + l15;                                       \
        uint32_t bd = Bs + brow * 128 +                                           \
                      (((((ksv) << 1) | hl) ^ (brow & 7)) << 4);                  \
        LDMATRIX_X4((bbuf)[np], bd);                                              \
    }                                                                             \
} while (0)

#define DO_MMA(abuf, bbuf) do {                                                   \
    _Pragma("unroll")                                                             \
    for (int np = 0; np < 4; np++)                                                \
        _Pragma("unroll")                                                         \
        for (int mt = 0; mt < 4; mt++) {                                          \
            MMA16816(d[mt][2 * np],     (abuf)[mt], (bbuf)[np][0], (bbuf)[np][2]);\
            MMA16816(d[mt][2 * np + 1], (abuf)[mt], (bbuf)[np][1], (bbuf)[np][3]);\
        }                                                                         \
} while (0)

#pragma unroll 1
    for (int c = 0; c < 8; c++) {
        if (c == 7) asm volatile("cp.async.wait_group 0;" ::: "memory");
        else        asm volatile("cp.async.wait_group 1;" ::: "memory");
        __syncthreads();
        if (c + 2 < 8) {
            load_stage(smem + ((c + 2) % 3) * STG, i0, j0, (c + 2) * 64, tid, diag);
            CP_COMMIT();
        }
        const uint32_t As = smem + (c % 3) * STG;
        const uint32_t Bs = diag ? As : (As + 16384);

        uint32_t af[2][4][4], bf[2][4][4];
        LOAD_FRAGS(af[0], bf[0], 0);
#pragma unroll
        for (int ks = 0; ks < 4; ks++) {
            if (ks < 3) LOAD_FRAGS(af[(ks + 1) & 1], bf[(ks + 1) & 1], ks + 1);
            DO_MMA(af[ks & 1], bf[ks & 1]);
        }
    }

    // ===== dual-sided epilogue =====
    float hpc[16], hnc[16];
#pragma unroll
    for (int k = 0; k < 16; k++) { hpc[k] = -BIGV; hnc[k] = BIGV; }

#pragma unroll
    for (int mt = 0; mt < 4; mt++) {
        int r0 = wr * 64 + mt * 16 + (lane >> 2);
        int li0 = s_labi[r0], li1 = s_labi[r0 + 8];
        float qi0 = s_qi[r0], qi1 = s_qi[r0 + 8];
        float hp0 = -BIGV, hp1 = -BIGV, hn0 = BIGV, hn1 = BIGV;
#pragma unroll
        for (int nt = 0; nt < 8; nt++) {
            int c0 = wc * 64 + nt * 8 + ((lane & 3) << 1);
            float q0 = s_qj[c0], q1 = s_qj[c0 + 1];
            int lj0 = s_labj[c0], lj1 = s_labj[c0 + 1];
            float g00 = d[mt][nt][0], g01 = d[mt][nt][1];
            float g10 = d[mt][nt][2], g11 = d[mt][nt][3];
            bool e00 = (li0 == lj0), e01 = (li0 == lj1);
            bool e10 = (li1 == lj0), e11 = (li1 == lj1);
            // row-side
            float m00 = fmaf(g00, -2.f, q0);
            float m01 = fmaf(g01, -2.f, q1);
            float m10 = fmaf(g10, -2.f, q0);
            float m11 = fmaf(g11, -2.f, q1);
            if (e00) hp0 = fmaxf(hp0, m00); else hn0 = fminf(hn0, m00);
            if (e01) hp0 = fmaxf(hp0, m01); else hn0 = fminf(hn0, m01);
            if (e10) hp1 = fmaxf(hp1, m10); else hn1 = fminf(hn1, m10);
            if (e11) hp1 = fmaxf(hp1, m11); else hn1 = fminf(hn1, m11);
            if (!diag) {
                // col-side
                float n00 = fmaf(g00, -2.f, qi0);
                float n01 = fmaf(g01, -2.f, qi0);
                float n10 = fmaf(g10, -2.f, qi1);
                float n11 = fmaf(g11, -2.f, qi1);
                int k0 = nt * 2, k1 = nt * 2 + 1;
                if (e00) hpc[k0] = fmaxf(hpc[k0], n00); else hnc[k0] = fminf(hnc[k0], n00);
                if (e10) hpc[k0] = fmaxf(hpc[k0], n10); else hnc[k0] = fminf(hnc[k0], n10);
                if (e01) hpc[k1] = fmaxf(hpc[k1], n01); else hnc[k1] = fminf(hnc[k1], n01);
                if (e11) hpc[k1] = fmaxf(hpc[k1], n11); else hnc[k1] = fminf(hnc[k1], n11);
            }
        }
        // row-side reduce across the 4 quad lanes
#pragma unroll
        for (int off = 1; off < 4; off <<= 1) {
            hp0 = fmaxf(hp0, __shfl_xor_sync(0xffffffffu, hp0, off));
            hp1 = fmaxf(hp1, __shfl_xor_sync(0xffffffffu, hp1, off));
            hn0 = fminf(hn0, __shfl_xor_sync(0xffffffffu, hn0, off));
            hn1 = fminf(hn1, __shfl_xor_sync(0xffffffffu, hn1, off));
        }
        if ((lane & 3) == 0) {
            hp_s[r0][wc] = hp0; hp_s[r0 + 8][wc] = hp1;
            hn_s[r0][wc] = hn0; hn_s[r0 + 8][wc] = hn1;
        }
    }

    if (!diag) {
        // col-side reduce across the 8 row-lanes
#pragma unroll
        for (int off = 4; off <= 16; off <<= 1) {
#pragma unroll
            for (int k = 0; k < 16; k++) {
                hpc[k] = fmaxf(hpc[k], __shfl_xor_sync(0xffffffffu, hpc[k], off));
                hnc[k] = fminf(hnc[k], __shfl_xor_sync(0xffffffffu, hnc[k], off));
            }
        }
        if ((lane >> 2) == 0) {
#pragma unroll
            for (int k = 0; k < 16; k++) {
                int col = wc * 64 + (k >> 1) * 8 + ((lane & 3) << 1) + (k & 1);
                hp_cs[col][wr] = hpc[k];
                hn_cs[col][wr] = hnc[k];
            }
        }
    }
    __syncthreads();
    {
        float hp = fmaxf(hp_s[tid][0], hp_s[tid][1]);
        float hn = fminf(hn_s[tid][0], hn_s[tid][1]);
        g_hp[tj][i0 + tid] = hp;
        g_hn[tj][i0 + tid] = hn;
        if (!diag) {
            float hpc2 = fmaxf(hp_cs[tid][0], hp_cs[tid][1]);
            float hnc2 = fminf(hn_cs[tid][0], hn_cs[tid][1]);
            g_hp[ti][j0 + tid] = hpc2;
            g_hn[ti][j0 + tid] = hnc2;
        }
    }
}

// ---------------------------------------------------------------------------
// Kernel 3: combine (16 blocks) + last-block final reduce.
// ---------------------------------------------------------------------------
__global__ void combine_kernel(const int* __restrict__ lab, float* __restrict__ out) {
    __shared__ int   cnt[512];
    __shared__ float ssum[256], scnt[256];
    const int tid = threadIdx.x;
    for (int i = tid; i < 512; i += 256) cnt[i] = 0;
    __syncthreads();
    for (int i = tid; i < B_SZ; i += 256) atomicAdd(&cnt[lab[i]], 1);
    __syncthreads();

    const int row = blockIdx.x * 256 + tid;
    float hp = -BIGV, hn = BIGV;
#pragma unroll
    for (int s = 0; s < NSPLIT; s++) {
        hp = fmaxf(hp, g_hp[s][row]);
        hn = fminf(hn, g_hn[s][row]);
    }
    int k = cnt[lab[row]];
    bool valid = (k >= 2) && (k < B_SZ);
    float p = g_p[row];
    float dp = sqrtf(fmaxf(p + hp, 0.f));
    float dn = sqrtf(fmaxf(p + hn, 0.f));
    float v = dp - dn + MARGIN;
    ssum[tid] = valid ? ((v > 0.f) ? v : 0.f) : 0.f;
    scnt[tid] = valid ? 1.f : 0.f;
    __syncthreads();
    for (int off = 128; off > 0; off >>= 1) {
        if (tid < off) { ssum[tid] += ssum[tid + off]; scnt[tid] += scnt[tid + off]; }
        __syncthreads();
    }
    if (tid == 0) {
        g_psum[blockIdx.x] = ssum[0];
        g_pcnt[blockIdx.x] = scnt[0];
        __threadfence();
        unsigned old = atomicAdd(&g_done, 1u);
        if (old == CBLKS - 1) {
            __threadfence();
            float s = 0.f, c = 0.f;
#pragma unroll
            for (int b = 0; b < CBLKS; b++) { s += g_psum[b]; c += g_pcnt[b]; }
            out[0] = (c > 0.f) ? (s / c) : 0.f;
            g_done = 0;     // reset for next graph replay
        }
    }
}

// ---------------------------------------------------------------------------
extern "C" void kernel_launch(void* const* d_in, const int* in_sizes, int n_in,
                              void* d_out, int out_size) {
    const float* E   = (const float*)d_in[0];
    const int*   lab = (const int*)d_in[1];
    float*       out = (float*)d_out;
    (void)in_sizes; (void)n_in; (void)out_size;

    cudaFuncSetAttribute(gemm_triplet_kernel,
                         cudaFuncAttributeMaxDynamicSharedMemorySize, DYN_SMEM);

    prep_stats_kernel<<<B_SZ / 8, 256>>>(E);
    gemm_triplet_kernel<<<NTILES, 128, DYN_SMEM>>>(lab);
    combine_kernel<<<CBLKS, 256>>>(lab, out);
}

// round 9
// speedup vs baseline: 1.1275x; 1.0081x over previous
#include <cuda_runtime.h>
#include <cuda_fp16.h>
#include <cstdint>

#define B_SZ   4096
#define D_SZ   512
#define MARGIN 0.5f
#define EPSV   1e-6f
#define BIGV   1e9f

#define NSPLIT (B_SZ / 128)                  // 32 tile rows/cols
#define NTILES (NSPLIT * (NSPLIT + 1) / 2)   // 528 upper-triangle tiles
#define STG    32768                         // bytes per stage (A 16K + B 16K)
#define DYN_SMEM (3 * STG)
#define CBLKS  16                            // combiner CTAs (bid < CBLKS)

// ---------------- device scratch (no cudaMalloc allowed) ----------------
__device__ __half Ehalf[B_SZ * D_SZ];
__device__ float  g_q[B_SZ];
__device__ float  g_p[B_SZ];
__device__ float  g_hp[NSPLIT][B_SZ];
__device__ float  g_hn[NSPLIT][B_SZ];
__device__ float  g_psum[CBLKS];
__device__ float  g_pcnt[CBLKS];
__device__ unsigned g_tiles_done;
__device__ unsigned g_done;

// ---------------- helpers ----------------
__device__ __forceinline__ uint32_t smem_u32(const void* p) {
    uint32_t a;
    asm("{ .reg .u64 t; cvta.to.shared.u64 t, %1; cvt.u32.u64 %0, t; }" : "=r"(a) : "l"(p));
    return a;
}

#define LDMATRIX_X4(r, addr)                                                      \
    asm volatile("ldmatrix.sync.aligned.m8n8.x4.shared.b16 {%0,%1,%2,%3}, [%4];"  \
        : "=r"((r)[0]), "=r"((r)[1]), "=r"((r)[2]), "=r"((r)[3]) : "r"(addr))

#define MMA16816(D, A, b0, b1)                                                    \
    asm volatile("mma.sync.aligned.m16n8k16.row.col.f32.f16.f16.f32 "             \
        "{%0,%1,%2,%3}, {%4,%5,%6,%7}, {%8,%9}, {%0,%1,%2,%3};"                   \
        : "+f"((D)[0]), "+f"((D)[1]), "+f"((D)[2]), "+f"((D)[3])                  \
        : "r"((A)[0]), "r"((A)[1]), "r"((A)[2]), "r"((A)[3]), "r"(b0), "r"(b1))

#define CP_ASYNC16(dst, src)                                                      \
    asm volatile("cp.async.cg.shared.global [%0], [%1], 16;"                      \
        :: "r"(dst), "l"(src) : "memory")
#define CP_COMMIT() asm volatile("cp.async.commit_group;" ::: "memory")

// load one 128x64-fp16 A tile (+ B tile unless diag) into a stage (xor swizzle)
// 128 threads: 8 chunks of 16B each per tile side.
__device__ __forceinline__ void load_stage(uint32_t base, int i0, int j0,
                                           int kc, int tid, bool diag) {
    uint32_t As = base, Bs = base + 16384;
#pragma unroll
    for (int it = 0; it < 8; it++) {
        int idx = tid + it * 128;
        int r = idx >> 3, ch = idx & 7;
        uint32_t dst = As + r * 128 + ((ch ^ (r & 7)) << 4);
        const void* src = &Ehalf[(size_t)(i0 + r) * D_SZ + kc + ch * 8];
        CP_ASYNC16(dst, src);
    }
    if (!diag) {
#pragma unroll
        for (int it = 0; it < 8; it++) {
            int idx = tid + it * 128;
            int r = idx >> 3, ch = idx & 7;
            uint32_t dst = Bs + r * 128 + ((ch ^ (r & 7)) << 4);
            const void* src = &Ehalf[(size_t)(j0 + r) * D_SZ + kc + ch * 8];
            CP_ASYNC16(dst, src);
        }
    }
}

// ---------------------------------------------------------------------------
// Kernel 1: fused fp32->fp16 convert + per-row stats. One warp per row.
// ---------------------------------------------------------------------------
__global__ void prep_stats_kernel(const float* __restrict__ E) {
    int warp = (blockIdx.x * blockDim.x + threadIdx.x) >> 5;
    int lane = threadIdx.x & 31;
    const float4* row = reinterpret_cast<const float4*>(E + (size_t)warp * D_SZ);
    uint2* hout = reinterpret_cast<uint2*>(Ehalf + (size_t)warp * D_SZ);
    float s = 0.f, sq = 0.f;
#pragma unroll
    for (int q = 0; q < 4; q++) {
        float4 v = row[lane + 32 * q];
        s  += v.x + v.y + v.z + v.w;
        sq += v.x * v.x + v.y * v.y + v.z * v.z + v.w * v.w;
        __half2 h0 = __floats2half2_rn(v.x, v.y);
        __half2 h1 = __floats2half2_rn(v.z, v.w);
        uint2 packed;
        packed.x = *reinterpret_cast<uint32_t*>(&h0);
        packed.y = *reinterpret_cast<uint32_t*>(&h1);
        hout[lane + 32 * q] = packed;
    }
#pragma unroll
    for (int off = 16; off > 0; off >>= 1) {
        s  += __shfl_xor_sync(0xffffffffu, s,  off);
        sq += __shfl_xor_sync(0xffffffffu, sq, off);
    }
    if (lane == 0) {
        g_q[warp] = sq - 2.f * EPSV * s;
        g_p[warp] = sq + 2.f * EPSV * s + (float)D_SZ * EPSV * EPSV;
    }
}

// ---------------------------------------------------------------------------
// Kernel 2: upper-triangle 128x128x512 gram tile + fused combine tail.
// ---------------------------------------------------------------------------
__global__ void __launch_bounds__(128, 2)
gemm_triplet_kernel(const int* __restrict__ lab, float* __restrict__ out) {
    extern __shared__ __align__(1024) char dsm[];
    __shared__ int   s_labi[128];
    __shared__ int   s_labj[128];
    __shared__ float s_qi[128];
    __shared__ float s_qj[128];
    __shared__ float hp_s[128][2];
    __shared__ float hn_s[128][2];
    __shared__ float hp_cs[128][2];
    __shared__ float hn_cs[128][2];
    __shared__ int   c_cnt[512];
    __shared__ float c_sum[128], c_cn[128];

    // map linear block id -> upper-triangle (ti, tj), ti <= tj
    int bid = blockIdx.x;
    int ti = 0, rem = bid;
    while (rem >= NSPLIT - ti) { rem -= NSPLIT - ti; ti++; }
    const int tj = ti + rem;
    const bool diag = (ti == tj);

    const int tid  = threadIdx.x;
    const int wid  = tid >> 5, lane = tid & 31;
    const int wr   = wid >> 1, wc = wid & 1;        // 2 x 2 warp grid
    const int hl   = lane >> 4;
    const int l15  = lane & 15;
    const int i0   = ti * 128;
    const int j0   = tj * 128;
    const uint32_t smem = smem_u32(dsm);

    s_labi[tid] = lab[i0 + tid];
    s_labj[tid] = lab[j0 + tid];
    s_qi[tid]   = g_q[i0 + tid];
    s_qj[tid]   = g_q[j0 + tid];

    float d[4][8][4];
#pragma unroll
    for (int a = 0; a < 4; a++)
#pragma unroll
        for (int b = 0; b < 8; b++)
#pragma unroll
            for (int e = 0; e < 4; e++) d[a][b][e] = 0.f;

    load_stage(smem + 0 * STG, i0, j0, 0,  tid, diag); CP_COMMIT();
    load_stage(smem + 1 * STG, i0, j0, 64, tid, diag); CP_COMMIT();

#define LOAD_FRAGS(abuf, bbuf, ksv) do {                                          \
    _Pragma("unroll")                                                             \
    for (int mt = 0; mt < 4; mt++) {                                              \
        int arow = wr * 64 + mt * 16 + l15;                                       \
        uint32_t ad = As + arow * 128 +                                           \
                      (((((ksv) << 1) | hl) ^ (arow & 7)) << 4);                  \
        LDMATRIX_X4((abuf)[mt], ad);                                              \
    }                                                                             \
    _Pragma("unroll")                                                             \
    for (int np = 0; np < 4; np++) {                                              \
        int brow = wc * 64 + np * 16 + l15;                                       \
        uint32_t bd = Bs + brow * 128 +                                           \
                      (((((ksv) << 1) | hl) ^ (brow & 7)) << 4);                  \
        LDMATRIX_X4((bbuf)[np], bd);                                              \
    }                                                                             \
} while (0)

#define DO_MMA(abuf, bbuf) do {                                                   \
    _Pragma("unroll")                                                             \
    for (int np = 0; np < 4; np++)                                                \
        _Pragma("unroll")                                                         \
        for (int mt = 0; mt < 4; mt++) {                                          \
            MMA16816(d[mt][2 * np],     (abuf)[mt], (bbuf)[np][0], (bbuf)[np][2]);\
            MMA16816(d[mt][2 * np + 1], (abuf)[mt], (bbuf)[np][1], (bbuf)[np][3]);\
        }                                                                         \
} while (0)

#pragma unroll 1
    for (int c = 0; c < 8; c++) {
        if (c == 7) asm volatile("cp.async.wait_group 0;" ::: "memory");
        else        asm volatile("cp.async.wait_group 1;" ::: "memory");
        __syncthreads();
        if (c + 2 < 8) {
            load_stage(smem + ((c + 2) % 3) * STG, i0, j0, (c + 2) * 64, tid, diag);
            CP_COMMIT();
        }
        const uint32_t As = smem + (c % 3) * STG;
        const uint32_t Bs = diag ? As : (As + 16384);

        uint32_t af[2][4][4], bf[2][4][4];
        LOAD_FRAGS(af[0], bf[0], 0);
#pragma unroll
        for (int ks = 0; ks < 4; ks++) {
            if (ks < 3) LOAD_FRAGS(af[(ks + 1) & 1], bf[(ks + 1) & 1], ks + 1);
            DO_MMA(af[ks & 1], bf[ks & 1]);
        }
    }

    // ===== dual-sided epilogue =====
    float hpc[16], hnc[16];
#pragma unroll
    for (int k = 0; k < 16; k++) { hpc[k] = -BIGV; hnc[k] = BIGV; }

#pragma unroll
    for (int mt = 0; mt < 4; mt++) {
        int r0 = wr * 64 + mt * 16 + (lane >> 2);
        int li0 = s_labi[r0], li1 = s_labi[r0 + 8];
        float qi0 = s_qi[r0], qi1 = s_qi[r0 + 8];
        float hp0 = -BIGV, hp1 = -BIGV, hn0 = BIGV, hn1 = BIGV;
#pragma unroll
        for (int nt = 0; nt < 8; nt++) {
            int c0 = wc * 64 + nt * 8 + ((lane & 3) << 1);
            float q0 = s_qj[c0], q1 = s_qj[c0 + 1];
            int lj0 = s_labj[c0], lj1 = s_labj[c0 + 1];
            float g00 = d[mt][nt][0], g01 = d[mt][nt][1];
            float g10 = d[mt][nt][2], g11 = d[mt][nt][3];
            bool e00 = (li0 == lj0), e01 = (li0 == lj1);
            bool e10 = (li1 == lj0), e11 = (li1 == lj1);
            float m00 = fmaf(g00, -2.f, q0);
            float m01 = fmaf(g01, -2.f, q1);
            float m10 = fmaf(g10, -2.f, q0);
            float m11 = fmaf(g11, -2.f, q1);
            if (e00) hp0 = fmaxf(hp0, m00); else hn0 = fminf(hn0, m00);
            if (e01) hp0 = fmaxf(hp0, m01); else hn0 = fminf(hn0, m01);
            if (e10) hp1 = fmaxf(hp1, m10); else hn1 = fminf(hn1, m10);
            if (e11) hp1 = fmaxf(hp1, m11); else hn1 = fminf(hn1, m11);
            if (!diag) {
                float n00 = fmaf(g00, -2.f, qi0);
                float n01 = fmaf(g01, -2.f, qi0);
                float n10 = fmaf(g10, -2.f, qi1);
                float n11 = fmaf(g11, -2.f, qi1);
                int k0 = nt * 2, k1 = nt * 2 + 1;
                if (e00) hpc[k0] = fmaxf(hpc[k0], n00); else hnc[k0] = fminf(hnc[k0], n00);
                if (e10) hpc[k0] = fmaxf(hpc[k0], n10); else hnc[k0] = fminf(hnc[k0], n10);
                if (e01) hpc[k1] = fmaxf(hpc[k1], n01); else hnc[k1] = fminf(hnc[k1], n01);
                if (e11) hpc[k1] = fmaxf(hpc[k1], n11); else hnc[k1] = fminf(hnc[k1], n11);
            }
        }
#pragma unroll
        for (int off = 1; off < 4; off <<= 1) {
            hp0 = fmaxf(hp0, __shfl_xor_sync(0xffffffffu, hp0, off));
            hp1 = fmaxf(hp1, __shfl_xor_sync(0xffffffffu, hp1, off));
            hn0 = fminf(hn0, __shfl_xor_sync(0xffffffffu, hn0, off));
            hn1 = fminf(hn1, __shfl_xor_sync(0xffffffffu, hn1, off));
        }
        if ((lane & 3) == 0) {
            hp_s[r0][wc] = hp0; hp_s[r0 + 8][wc] = hp1;
            hn_s[r0][wc] = hn0; hn_s[r0 + 8][wc] = hn1;
        }
    }

    if (!diag) {
#pragma unroll
        for (int off = 4; off <= 16; off <<= 1) {
#pragma unroll
            for (int k = 0; k < 16; k++) {
                hpc[k] = fmaxf(hpc[k], __shfl_xor_sync(0xffffffffu, hpc[k], off));
                hnc[k] = fminf(hnc[k], __shfl_xor_sync(0xffffffffu, hnc[k], off));
            }
        }
        if ((lane >> 2) == 0) {
#pragma unroll
            for (int k = 0; k < 16; k++) {
                int col = wc * 64 + (k >> 1) * 8 + ((lane & 3) << 1) + (k & 1);
                hp_cs[col][wr] = hpc[k];
                hn_cs[col][wr] = hnc[k];
            }
        }
    }
    __syncthreads();
    {
        float hp = fmaxf(hp_s[tid][0], hp_s[tid][1]);
        float hn = fminf(hn_s[tid][0], hn_s[tid][1]);
        g_hp[tj][i0 + tid] = hp;
        g_hn[tj][i0 + tid] = hn;
        if (!diag) {
            float hpc2 = fmaxf(hp_cs[tid][0], hp_cs[tid][1]);
            float hnc2 = fminf(hn_cs[tid][0], hn_cs[tid][1]);
            g_hp[ti][j0 + tid] = hpc2;
            g_hn[ti][j0 + tid] = hnc2;
        }
    }

    // signal this tile complete
    __threadfence();
    __syncthreads();
    if (tid == 0) atomicAdd(&g_tiles_done, 1u);

    // ===== fused combine tail: CTAs 0..15 each handle 256 anchors =====
    if (bid < CBLKS) {
        if (tid == 0) {
            while (atomicAdd(&g_tiles_done, 0u) < NTILES) { __nanosleep(64); }
        }
        __syncthreads();
        __threadfence();    // acquire: all g_hp/g_hn visible

        for (int i = tid; i < 512; i += 128) c_cnt[i] = 0;
        __syncthreads();
        for (int i = tid; i < B_SZ; i += 128) atomicAdd(&c_cnt[lab[i]], 1);
        __syncthreads();

        float lsum = 0.f, lcnt = 0.f;
#pragma unroll
        for (int rr = 0; rr < 2; rr++) {
            const int row = bid * 256 + rr * 128 + tid;
            float hp = -BIGV, hn = BIGV;
#pragma unroll
            for (int s = 0; s < NSPLIT; s++) {
                hp = fmaxf(hp, g_hp[s][row]);
                hn = fminf(hn, g_hn[s][row]);
            }
            int k = c_cnt[lab[row]];
            bool valid = (k >= 2) && (k < B_SZ);
            float p = g_p[row];
            float dp = sqrtf(fmaxf(p + hp, 0.f));
            float dn = sqrtf(fmaxf(p + hn, 0.f));
            float v = dp - dn + MARGIN;
            if (valid) { lsum += (v > 0.f) ? v : 0.f; lcnt += 1.f; }
        }
        c_sum[tid] = lsum; c_cn[tid] = lcnt;
        __syncthreads();
        for (int off = 64; off > 0; off >>= 1) {
            if (tid < off) { c_sum[tid] += c_sum[tid + off]; c_cn[tid] += c_cn[tid + off]; }
            __syncthreads();
        }
        if (tid == 0) {
            g_psum[bid] = c_sum[0];
            g_pcnt[bid] = c_cn[0];
            __threadfence();
            unsigned old = atomicAdd(&g_done, 1u);
            if (old == CBLKS - 1) {
                __threadfence();
                float s = 0.f, c = 0.f;
#pragma unroll
                for (int b = 0; b < CBLKS; b++) { s += g_psum[b]; c += g_pcnt[b]; }
                out[0] = (c > 0.f) ? (s / c) : 0.f;
                g_done = 0;          // reset for next graph replay
                g_tiles_done = 0;
                __threadfence();
            }
        }
    }
}

// ---------------------------------------------------------------------------
extern "C" void kernel_launch(void* const* d_in, const int* in_sizes, int n_in,
                              void* d_out, int out_size) {
    const float* E   = (const float*)d_in[0];
    const int*   lab = (const int*)d_in[1];
    float*       out = (float*)d_out;
    (void)in_sizes; (void)n_in; (void)out_size;

    cudaFuncSetAttribute(gemm_triplet_kernel,
                         cudaFuncAttributeMaxDynamicSharedMemorySize, DYN_SMEM);

    prep_stats_kernel<<<B_SZ / 8, 256>>>(E);
    gemm_triplet_kernel<<<NTILES, 128, DYN_SMEM>>>(lab, out);
}